// round 16
// baseline (speedup 1.0000x reference)
#include <cuda_runtime.h>
#include <cuda_bf16.h>
#include <math.h>

// Problem constants
#define BATCH 2
#define DGRID 128
#define DMID  125          // after 4^3 composed conv
#define DOUT  123          // after 3^3 conv
#define CIN   3
#define CMID  5
#define COUT  3

#define NVOX_MID ((size_t)BATCH*DMID*DMID*DMID)   // 3,906,250

// ---------------- device scratch ----------------
// mid grid split into two planes: ch0-3 (float4) + ch4 (float)
__device__ float4 g_midA[NVOX_MID + 8];   // 62.5 MB
__device__ float  g_midB[NVOX_MID + 8];   // 15.6 MB

// ---------------- Stage A: sparse scatter with on-the-fly composed weights ----
// grid: (ceil(n/128), 4); blockIdx.y = kz; ky,kx in-register loops
__global__ __launch_bounds__(128)
void scatterA_kernel(const int* __restrict__ coords,
                     const float* __restrict__ voxels,
                     const float* __restrict__ W1,
                     const float* __restrict__ W2, int n) {
    __shared__ float wsm[240];     // [ky][kx][ci][c5]

    const int kz = blockIdx.y;

    // ---- compose W12[kz][ky][kx][ci][c5] for ky,kx = 0..3 ----
    for (int idx = threadIdx.x; idx < 240; idx += 128) {
        int ky = idx / 60;
        int kx = (idx / 15) & 3;
        int r  = idx % 15;
        int ci = r / 5, c5 = r % 5;
        float s = 0.f;
        #pragma unroll
        for (int az = 0; az < 2; az++) {
            int bz = kz - az; if (bz < 0 || bz > 2) continue;
            #pragma unroll
            for (int ay = 0; ay < 2; ay++) {
                int by = ky - ay; if (by < 0 || by > 2) continue;
                #pragma unroll
                for (int ax = 0; ax < 2; ax++) {
                    int bx = kx - ax; if (bx < 0 || bx > 2) continue;
                    const float* w1 = W1 + (((az*2 + ay)*2 + ax)*3 + ci)*9;
                    const float* w2 = W2 + ((bz*3 + by)*3 + bx)*9*5;
                    #pragma unroll
                    for (int m = 0; m < 9; m++)
                        s += w1[m] * w2[m*5 + c5];
                }
            }
        }
        wsm[idx] = s;
    }
    __syncthreads();

    const int v = blockIdx.x * blockDim.x + threadIdx.x;
    if (v >= n) return;

    const int4 c = ((const int4*)coords)[v];         // (b, z, y, x)
    const int oz = c.y - kz;
    if ((unsigned)oz >= (unsigned)DMID) return;

    const float v0 = __ldg(voxels + 3*v + 0);
    const float v1 = __ldg(voxels + 3*v + 1);
    const float v2 = __ldg(voxels + 3*v + 2);

    const size_t zbase = (((size_t)c.x*DMID + oz)*DMID);

    #pragma unroll
    for (int ky = 0; ky < 4; ky++) {
        int oy = c.z - ky;
        if ((unsigned)oy >= (unsigned)DMID) continue;
        const size_t rowbase = (zbase + oy)*DMID;
        #pragma unroll
        for (int kx = 0; kx < 4; kx++) {
            int ox = c.w - kx;
            if ((unsigned)ox >= (unsigned)DMID) continue;
            const float* w = wsm + (ky*4 + kx)*15;
            float s0 = v0*w[0]  + v1*w[5]  + v2*w[10];
            float s1 = v0*w[1]  + v1*w[6]  + v2*w[11];
            float s2 = v0*w[2]  + v1*w[7]  + v2*w[12];
            float s3 = v0*w[3]  + v1*w[8]  + v2*w[13];
            float s4 = v0*w[4]  + v1*w[9]  + v2*w[14];

            float4* pA = g_midA + rowbase + ox;
            float*  pB = g_midB + rowbase + ox;
            asm volatile("red.global.add.v4.f32 [%0], {%1, %2, %3, %4};"
                         :: "l"(pA), "f"(s0), "f"(s1), "f"(s2), "f"(s3) : "memory");
            asm volatile("red.global.add.f32 [%0], %1;"
                         :: "l"(pB), "f"(s4) : "memory");
        }
    }
}

// ================= Stage B: 3^3 conv, 5ch -> 3ch, +bias, relu =================
// block (8,4,4); tile 32 x 8 x 8 outputs; each thread: 8 x-outputs x 2 z-outputs
#define BTY 8
#define BBX 4
#define BTZ 4               // thread z dim; each covers 2 z outputs
#define BRX 8
#define RZ  2
#define BTX (BBX*BRX)        // 32
#define TILEZ (BTZ*RZ)       // 8
#define BSZ (TILEZ+2)        // 10
#define BSY (BTY+2)          // 10
#define BSXV 34              // voxels per smem row (32+2)
#define SRA 140              // planeA row stride, floats (136 used; 560B == 48 mod 128)
#define SRB 36               // planeB row stride, floats (34 used; 144B == 16 mod 128)
#define BW_ROW 48            // padded weight row stride (45 used)
#define STG_ROW 98           // staging row stride (96 used; 98%32=2)

#define SMA_FLOATS (BSZ*BSY*SRA)   // 14000
#define SMB_FLOATS (BSZ*BSY*SRB)   // 3600
#define SMEM_TOT_F (SMA_FLOATS + SMB_FLOATS + 9*BW_ROW)   // 18032 floats = 72128 B

__global__ __launch_bounds__(128, 3)
void convB_kernel(const float* __restrict__ W3, const float* __restrict__ b3,
                  float* __restrict__ out) {
    extern __shared__ float smem[];
    float* smA = smem;
    float* smB = smem + SMA_FLOATS;
    float* wsm = smB + SMB_FLOATS;

    const int ty  = threadIdx.x;           // 0..7  (fast lane dim, y within tile)
    const int txc = threadIdx.y;           // 0..3  (x chunk)
    const int tz  = threadIdx.z;           // 0..3  (z pair index)
    const int tid = ty + BTY*(txc + BBX*tz);

    const int x0 = blockIdx.x * BTX;
    const int y0 = blockIdx.y * BTY;
    const int NBZ = (DOUT + TILEZ - 1) / TILEZ;   // 16
    const int b  = blockIdx.z / NBZ;
    const int z0 = (blockIdx.z % NBZ) * TILEZ;

    // ---- tile load: (y,x) outer / z inner ----
    {
        const float4* srcA = g_midA + (size_t)b*DMID*DMID*DMID;
        const float*  srcB = g_midB + (size_t)b*DMID*DMID*DMID;
        #pragma unroll 1
        for (int i = tid; i < BSY*BSXV; i += 128) {    // 340 -> ~3 iters
            int yy = i / BSXV;
            int xx = i - yy*BSXV;
            int gy = min(y0 + yy, DMID-1);
            int gx = min(x0 + xx, DMID-1);
            size_t s0 = (size_t)gy*DMID + gx;
            int dA = yy*SRA + xx*4;
            int dB = yy*SRB + xx;
            #pragma unroll
            for (int zz = 0; zz < BSZ; zz++) {
                int gz = min(z0 + zz, DMID-1);
                size_t s = (size_t)gz*(DMID*DMID) + s0;
                *(float4*)&smA[zz*(BSY*SRA) + dA] = __ldg(srcA + s);
                smB[zz*(BSY*SRB) + dB] = __ldg(srcB + s);
            }
        }
        for (int i = tid; i < 9*45; i += 128) {
            int row = i / 45, t = i - row*45;
            wsm[row*BW_ROW + t] = W3[row*45 + t];
        }
    }
    __syncthreads();

    float acc[RZ][BRX][COUT];
    #pragma unroll
    for (int rz = 0; rz < RZ; rz++)
        #pragma unroll
        for (int j = 0; j < BRX; j++)
            #pragma unroll
            for (int c = 0; c < COUT; c++) acc[rz][j][c] = 0.f;

    // mainloop: for each ky, walk 4 z-rows; each row feeds up to 2 (rz,kz) pairs
    #pragma unroll 1
    for (int ky = 0; ky < 3; ky++) {
        #pragma unroll 1
        for (int r = 0; r < 4; r++) {
            const int zrow = 2*tz + r;
            // load row windows
            const float4* rpA = (const float4*)&smA[(zrow*BSY + (ty + ky))*SRA + txc*(BRX*4)];
            union { float4 q[10]; float f[40]; } ra;
            #pragma unroll
            for (int i = 0; i < 10; i++) ra.q[i] = rpA[i];
            const float4* rpB = (const float4*)&smB[(zrow*BSY + (ty + ky))*SRB + txc*BRX];
            union { float4 q[3]; float f[12]; } rb;
            #pragma unroll
            for (int i = 0; i < 3; i++) rb.q[i] = rpB[i];

            #pragma unroll
            for (int rz = 0; rz < RZ; rz++) {
                const int kz = r - rz;
                if (kz < 0 || kz > 2) continue;
                const float* wp = wsm + (kz*3 + ky)*BW_ROW;   // 15 taps x 3 cout
                #pragma unroll
                for (int kx = 0; kx < 3; kx++) {
                    #pragma unroll
                    for (int ci = 0; ci < 4; ci++) {
                        const int t = kx*5 + ci;
                        float w0 = wp[t*3+0], w1 = wp[t*3+1], w2 = wp[t*3+2];
                        #pragma unroll
                        for (int j = 0; j < BRX; j++) {
                            float xv = ra.f[(j + kx)*4 + ci];
                            acc[rz][j][0] = fmaf(xv, w0, acc[rz][j][0]);
                            acc[rz][j][1] = fmaf(xv, w1, acc[rz][j][1]);
                            acc[rz][j][2] = fmaf(xv, w2, acc[rz][j][2]);
                        }
                    }
                    {   // ci = 4 from planeB
                        const int t = kx*5 + 4;
                        float w0 = wp[t*3+0], w1 = wp[t*3+1], w2 = wp[t*3+2];
                        #pragma unroll
                        for (int j = 0; j < BRX; j++) {
                            float xv = rb.f[j + kx];
                            acc[rz][j][0] = fmaf(xv, w0, acc[rz][j][0]);
                            acc[rz][j][1] = fmaf(xv, w1, acc[rz][j][1]);
                            acc[rz][j][2] = fmaf(xv, w2, acc[rz][j][2]);
                        }
                    }
                }
            }
        }
    }

    // ---- epilogue: bias + relu, stage through smem (output-linear), coalesced store ----
    const float bb0 = b3[0], bb1 = b3[1], bb2 = b3[2];
    __syncthreads();                 // mainloop reads done; reuse smA as staging
    {
        // staging rows: [z2(8)][ty(8)] x STG_ROW floats; 96 used = (txc,j,c)
        #pragma unroll
        for (int rz = 0; rz < RZ; rz++) {
            float* s = smA + ((2*tz + rz)*BTY + ty)*STG_ROW + txc*(BRX*3);
            #pragma unroll
            for (int j = 0; j < BRX; j++) {
                s[j*3+0] = fmaxf(acc[rz][j][0] + bb0, 0.f);
                s[j*3+1] = fmaxf(acc[rz][j][1] + bb1, 0.f);
                s[j*3+2] = fmaxf(acc[rz][j][2] + bb2, 0.f);
            }
        }
    }
    __syncthreads();
    {
        // div-free: thread owns (row = tid>>1, half = tid&1) -> 48 floats
        const int row = tid >> 1;            // z2*8 + ty2, 0..63
        const int half = tid & 1;
        const int z2 = row >> 3, ty2 = row & 7;
        const int oz = z0 + z2, oy = y0 + ty2;
        if (oz < DOUT && oy < DOUT) {
            const int oxcap = (min(DOUT - x0, BTX)) * 3;   // valid floats in this row
            const int base  = half * 48;
            const float* s = smA + row*STG_ROW + base;
            float* d = out + (((size_t)b*DOUT + oz)*DOUT + oy)*(size_t)(DOUT*3)
                     + (size_t)x0*3 + base;
            const int cap = oxcap - base;
            #pragma unroll
            for (int j = 0; j < 48; j++)
                if (j < cap) d[j] = s[j];
        }
    }
}

// ---------------- launch ----------------
extern "C" void kernel_launch(void* const* d_in, const int* in_sizes, int n_in,
                              void* d_out, int out_size) {
    const int*   coords = (const int*)  d_in[0];
    const float* voxels = (const float*)d_in[1];
    const float* W1     = (const float*)d_in[2];
    const float* W2     = (const float*)d_in[3];
    const float* W3     = (const float*)d_in[4];
    const float* b3     = (const float*)d_in[5];
    float*       out    = (float*)d_out;

    const int n = in_sizes[0] / 4;

    // zero the two mid planes (62.5 MB + 15.6 MB)
    void* pA = nullptr; void* pB = nullptr;
    cudaGetSymbolAddress(&pA, g_midA);
    cudaGetSymbolAddress(&pB, g_midB);
    cudaMemsetAsync(pA, 0, NVOX_MID*sizeof(float4));
    cudaMemsetAsync(pB, 0, NVOX_MID*sizeof(float));

    // Stage A: sparse scatter conv (thread = voxel x kz; ky,kx loops)
    {
        dim3 block(128);
        dim3 grid((n + 127)/128, 4);
        scatterA_kernel<<<grid, block>>>(coords, voxels, W1, W2, n);
    }

    // Stage B: 3^3 conv 5->3 + bias + relu (z-register-blocked)
    {
        const size_t smem_bytes = (size_t)SMEM_TOT_F * sizeof(float);   // 72128 B
        cudaFuncSetAttribute(convB_kernel,
                             cudaFuncAttributeMaxDynamicSharedMemorySize,
                             (int)smem_bytes);
        dim3 block(BTY, BBX, BTZ);                    // (8,4,4) = 128
        dim3 grid((DOUT + BTX - 1)/BTX,               // 4
                  (DOUT + BTY - 1)/BTY,               // 16
                  BATCH * ((DOUT + TILEZ - 1)/TILEZ)); // 32
        convB_kernel<<<grid, block, smem_bytes>>>(W3, b3, out);
    }
}

// round 17
// speedup vs baseline: 1.0762x; 1.0762x over previous
#include <cuda_runtime.h>
#include <cuda_bf16.h>
#include <math.h>

// Problem constants
#define BATCH 2
#define DGRID 128
#define DMID  125          // after 4^3 composed conv
#define DOUT  123          // after 3^3 conv
#define CIN   3
#define CMID  5
#define COUT  3

#define NVOX_MID ((size_t)BATCH*DMID*DMID*DMID)   // 3,906,250

// ---------------- device scratch: one buffer, two planes ----------------
// planeA: NVOX_MID float4 (ch0-3), then planeB: NVOX_MID float (ch4)
#define MID_F4_COUNT (NVOX_MID + (NVOX_MID + 3)/4 + 16)
__device__ float4 g_mid[MID_F4_COUNT];     // 78.1 MB total

__device__ __forceinline__ float4* planeA_base() { return g_mid; }
__device__ __forceinline__ float*  planeB_base() { return (float*)(g_mid + NVOX_MID); }

// ---------------- Stage A: sparse scatter, all 64 taps per thread ----------------
// grid: ceil(n/256); each block composes all 960 W12 coefficients once.
__global__ __launch_bounds__(256)
void scatterA_kernel(const int* __restrict__ coords,
                     const float* __restrict__ voxels,
                     const float* __restrict__ W1,
                     const float* __restrict__ W2, int n) {
    __shared__ float wsm[960];     // [kz][ky][kx][ci][c5]

    // ---- compose W12 for all taps ----
    for (int idx = threadIdx.x; idx < 960; idx += 256) {
        int kz = idx / 240;
        int ky = (idx / 60) & 3;
        int kx = (idx / 15) & 3;
        int r  = idx % 15;
        int ci = r / 5, c5 = r % 5;
        float s = 0.f;
        #pragma unroll
        for (int az = 0; az < 2; az++) {
            int bz = kz - az; if (bz < 0 || bz > 2) continue;
            #pragma unroll
            for (int ay = 0; ay < 2; ay++) {
                int by = ky - ay; if (by < 0 || by > 2) continue;
                #pragma unroll
                for (int ax = 0; ax < 2; ax++) {
                    int bx = kx - ax; if (bx < 0 || bx > 2) continue;
                    const float* w1 = W1 + (((az*2 + ay)*2 + ax)*3 + ci)*9;
                    const float* w2 = W2 + ((bz*3 + by)*3 + bx)*9*5;
                    #pragma unroll
                    for (int m = 0; m < 9; m++)
                        s += w1[m] * w2[m*5 + c5];
                }
            }
        }
        wsm[idx] = s;
    }
    __syncthreads();

    const int v = blockIdx.x * blockDim.x + threadIdx.x;
    if (v >= n) return;

    const int4 c = ((const int4*)coords)[v];         // (b, z, y, x)
    const float v0 = __ldg(voxels + 3*v + 0);
    const float v1 = __ldg(voxels + 3*v + 1);
    const float v2 = __ldg(voxels + 3*v + 2);

    float4* pAb = planeA_base();
    float*  pBb = planeB_base();
    const size_t bbase = (size_t)c.x*DMID*DMID*DMID;

    #pragma unroll 1
    for (int kz = 0; kz < 4; kz++) {
        int oz = c.y - kz;
        if ((unsigned)oz >= (unsigned)DMID) continue;
        const size_t zbase = bbase + (size_t)oz*DMID*DMID;
        #pragma unroll 1
        for (int ky = 0; ky < 4; ky++) {
            int oy = c.z - ky;
            if ((unsigned)oy >= (unsigned)DMID) continue;
            const size_t rowbase = zbase + (size_t)oy*DMID;
            const float* wrow = wsm + (kz*16 + ky*4)*15;
            #pragma unroll
            for (int kx = 0; kx < 4; kx++) {
                int ox = c.w - kx;
                if ((unsigned)ox >= (unsigned)DMID) continue;
                const float* w = wrow + kx*15;
                float s0 = v0*w[0]  + v1*w[5]  + v2*w[10];
                float s1 = v0*w[1]  + v1*w[6]  + v2*w[11];
                float s2 = v0*w[2]  + v1*w[7]  + v2*w[12];
                float s3 = v0*w[3]  + v1*w[8]  + v2*w[13];
                float s4 = v0*w[4]  + v1*w[9]  + v2*w[14];

                asm volatile("red.global.add.v4.f32 [%0], {%1, %2, %3, %4};"
                             :: "l"(pAb + rowbase + ox),
                                "f"(s0), "f"(s1), "f"(s2), "f"(s3) : "memory");
                asm volatile("red.global.add.f32 [%0], %1;"
                             :: "l"(pBb + rowbase + ox), "f"(s4) : "memory");
            }
        }
    }
}

// ================= Stage B: 3^3 conv, 5ch -> 3ch, +bias, relu (R15 proven) ====
// block (8,4,4): threadIdx.x = ty (fast lane dim), .y = x-chunk, .z = tz
#define BTY 8
#define BBX 4
#define BTZ 4
#define BRX 8
#define BTX (BBX*BRX)        // 32
#define BSZ (BTZ+2)          // 6
#define BSY (BTY+2)          // 10
#define BSXV 34              // voxels per smem row (32+2)
#define SRA 140              // planeA row stride, floats (136 used; 560B == 48 mod 128)
#define SRB 36               // planeB row stride, floats (34 used; 144B == 16 mod 128)
#define BW_ROW 48            // padded weight row stride (45 used)
#define STG_ROW 98           // staging row stride, floats (96 used; 98%32=2)

__global__ __launch_bounds__(128, 5)
void convB_kernel(const float* __restrict__ W3, const float* __restrict__ b3,
                  float* __restrict__ out) {
    __shared__ float smA[BSZ*BSY*SRA];     // 8400 floats
    __shared__ float smB[BSZ*BSY*SRB];     // 2160 floats
    __shared__ float wsm[9*BW_ROW];        // 432 floats

    const int ty  = threadIdx.x;           // 0..7  (fast lane dim, y within tile)
    const int txc = threadIdx.y;           // 0..3  (x chunk)
    const int tz  = threadIdx.z;           // 0..3  (z within tile)
    const int tid = ty + BTY*(txc + BBX*tz);

    const int x0 = blockIdx.x * BTX;
    const int y0 = blockIdx.y * BTY;
    const int NBZ = (DOUT + BTZ - 1) / BTZ;   // 31
    const int b  = blockIdx.z / NBZ;
    const int z0 = (blockIdx.z % NBZ) * BTZ;

    // ---- tile load: (y,x) outer / z inner, minimal index math ----
    {
        const float4* srcA = planeA_base() + (size_t)b*DMID*DMID*DMID;
        const float*  srcB = planeB_base() + (size_t)b*DMID*DMID*DMID;
        #pragma unroll 1
        for (int i = tid; i < BSY*BSXV; i += 128) {    // 340 -> ~3 iters
            int yy = i / BSXV;
            int xx = i - yy*BSXV;
            int gy = min(y0 + yy, DMID-1);
            int gx = min(x0 + xx, DMID-1);
            size_t s0 = (size_t)gy*DMID + gx;
            int dA = yy*SRA + xx*4;
            int dB = yy*SRB + xx;
            #pragma unroll
            for (int zz = 0; zz < BSZ; zz++) {
                int gz = min(z0 + zz, DMID-1);
                size_t s = (size_t)gz*(DMID*DMID) + s0;
                *(float4*)&smA[zz*(BSY*SRA) + dA] = __ldg(srcA + s);
                smB[zz*(BSY*SRB) + dB] = __ldg(srcB + s);
            }
        }
        for (int i = tid; i < 9*45; i += 128) {
            int row = i / 45, t = i - row*45;
            wsm[row*BW_ROW + t] = W3[row*45 + t];
        }
    }
    __syncthreads();

    float acc[BRX][COUT];
    #pragma unroll
    for (int j = 0; j < BRX; j++)
        #pragma unroll
        for (int c = 0; c < COUT; c++) acc[j][c] = 0.f;

    #pragma unroll 1
    for (int kz = 0; kz < 3; kz++) {
        #pragma unroll 1
        for (int ky = 0; ky < 3; ky++) {
            // planeA: 10 float4 sliding window (ch0-3 for voxels txc*8 .. txc*8+9)
            const float4* rpA = (const float4*)&smA[((tz + kz)*BSY + (ty + ky))*SRA + txc*(BRX*4)];
            union { float4 q[10]; float f[40]; } ra;
            #pragma unroll
            for (int i = 0; i < 10; i++) ra.q[i] = rpA[i];
            // planeB: 12 floats (10 used) as 3 float4
            const float4* rpB = (const float4*)&smB[((tz + kz)*BSY + (ty + ky))*SRB + txc*BRX];
            union { float4 q[3]; float f[12]; } rb;
            #pragma unroll
            for (int i = 0; i < 3; i++) rb.q[i] = rpB[i];

            const float* wp = wsm + (kz*3 + ky)*BW_ROW;   // 15 taps x 3 cout

            #pragma unroll
            for (int kx = 0; kx < 3; kx++) {
                #pragma unroll
                for (int ci = 0; ci < 4; ci++) {
                    const int t = kx*5 + ci;
                    float w0 = wp[t*3+0], w1 = wp[t*3+1], w2 = wp[t*3+2];
                    #pragma unroll
                    for (int j = 0; j < BRX; j++) {
                        float xv = ra.f[(j + kx)*4 + ci];
                        acc[j][0] = fmaf(xv, w0, acc[j][0]);
                        acc[j][1] = fmaf(xv, w1, acc[j][1]);
                        acc[j][2] = fmaf(xv, w2, acc[j][2]);
                    }
                }
                {   // ci = 4 from planeB
                    const int t = kx*5 + 4;
                    float w0 = wp[t*3+0], w1 = wp[t*3+1], w2 = wp[t*3+2];
                    #pragma unroll
                    for (int j = 0; j < BRX; j++) {
                        float xv = rb.f[j + kx];
                        acc[j][0] = fmaf(xv, w0, acc[j][0]);
                        acc[j][1] = fmaf(xv, w1, acc[j][1]);
                        acc[j][2] = fmaf(xv, w2, acc[j][2]);
                    }
                }
            }
        }
    }

    // ---- epilogue: bias + relu, stage through smem (output-linear), coalesced store ----
    const float bb0 = b3[0], bb1 = b3[1], bb2 = b3[2];
    __syncthreads();                 // mainloop reads done; reuse smA as staging
    {
        // staging layout: [tz][ty] rows of STG_ROW floats, 96 used = (txc,j,c)
        float* s = smA + (tz*BTY + ty)*STG_ROW + txc*(BRX*3);
        #pragma unroll
        for (int j = 0; j < BRX; j++) {
            s[j*3+0] = fmaxf(acc[j][0] + bb0, 0.f);
            s[j*3+1] = fmaxf(acc[j][1] + bb1, 0.f);
            s[j*3+2] = fmaxf(acc[j][2] + bb2, 0.f);
        }
    }
    __syncthreads();
    {
        // div-free: thread owns (row = tid>>2, quarter = tid&3) -> 24 floats
        const int row = tid >> 2;            // tz2*8 + ty2
        const int q   = tid & 3;
        const int tz2 = row >> 3, ty2 = row & 7;
        const int oz = z0 + tz2, oy = y0 + ty2;
        if (oz < DOUT && oy < DOUT) {
            const int oxcap = (min(DOUT - x0, BTX)) * 3;   // valid floats in this row
            const int base  = q * 24;
            const float* s = smA + row*STG_ROW + base;
            float* d = out + (((size_t)b*DOUT + oz)*DOUT + oy)*(size_t)(DOUT*3)
                     + (size_t)x0*3 + base;
            const int cap = oxcap - base;                  // 24 interior; 24/24/24/9 edge
            #pragma unroll
            for (int j = 0; j < 24; j++)
                if (j < cap) d[j] = s[j];
        }
    }
}

// ---------------- launch ----------------
extern "C" void kernel_launch(void* const* d_in, const int* in_sizes, int n_in,
                              void* d_out, int out_size) {
    const int*   coords = (const int*)  d_in[0];
    const float* voxels = (const float*)d_in[1];
    const float* W1     = (const float*)d_in[2];
    const float* W2     = (const float*)d_in[3];
    const float* W3     = (const float*)d_in[4];
    const float* b3     = (const float*)d_in[5];
    float*       out    = (float*)d_out;

    const int n = in_sizes[0] / 4;

    // zero both mid planes with ONE memset (planes live in one buffer)
    void* pmid = nullptr;
    cudaGetSymbolAddress(&pmid, g_mid);
    cudaMemsetAsync(pmid, 0, (NVOX_MID*5)*sizeof(float));

    // Stage A: sparse scatter conv (thread = voxel, all 64 taps)
    {
        dim3 block(256);
        dim3 grid((n + 255)/256);
        scatterA_kernel<<<grid, block>>>(coords, voxels, W1, W2, n);
    }

    // Stage B: 3^3 conv 5->3 + bias + relu
    {
        dim3 block(BTY, BBX, BTZ);                 // (8,4,4) = 128
        dim3 grid((DOUT + BTX - 1)/BTX,            // 4
                  (DOUT + BTY - 1)/BTY,            // 16
                  BATCH * ((DOUT + BTZ - 1)/BTZ)); // 62
        convB_kernel<<<grid, block>>>(W3, b3, out);
    }
}